// round 13
// baseline (speedup 1.0000x reference)
#include <cuda_runtime.h>
#include <math.h>

#define NB   32
#define RESO 256
#define KK   1024
#define EPSF 1e-6f
#define JCH  32            // j's per block
#define NOCT 4             // i-octants (warps) per block
#define IO   (KK / NOCT)   // 256 i's per thread

// log2(e)^2 and ln(2)
#define LOG2E2  2.0813689810056077f
#define LN2     0.6931471805599453f

typedef unsigned long long ull;

// Scratch (no allocations allowed).
// src: (sx, sy, |s|^2 * log2e^2, 0)   trg: (tx', ty', |t'|^2, 0), t' = t - eps
__device__ float4 g_src4[NB * KK];
__device__ float4 g_trg4[NB * KK];
__device__ double g_loss;
__device__ double g_vis;
__device__ unsigned int g_done;

__device__ __forceinline__ float rsq_approx(float x) {
    float r; asm("rsqrt.approx.f32 %0, %1;" : "=f"(r) : "f"(x)); return r;
}
__device__ __forceinline__ float sqrt_approx(float x) {
    float r; asm("sqrt.approx.f32 %0, %1;" : "=f"(r) : "f"(x)); return r;
}
__device__ __forceinline__ float lg2_approx(float x) {
    float r; asm("lg2.approx.f32 %0, %1;" : "=f"(r) : "f"(x)); return r;
}

// Two exponentials through ONE MUFU ex2.approx.f16x2 op.
__device__ __forceinline__ void ex2_pair(float e0, float e1, float& r0, float& r1) {
    asm("{\n\t"
        ".reg .b32 h;\n\t"
        ".reg .f16 a, b;\n\t"
        "cvt.rn.f16x2.f32 h, %2, %3;\n\t"
        "ex2.approx.f16x2 h, h;\n\t"
        "mov.b32 {a, b}, h;\n\t"
        "cvt.f32.f16 %0, a;\n\t"
        "cvt.f32.f16 %1, b;\n\t"
        "}" : "=f"(r0), "=f"(r1) : "f"(e0), "f"(e1));
}

// packed f32x2 ops (Blackwell; PTX-only)
__device__ __forceinline__ ull fma2(ull a, ull b, ull c) {
    ull r; asm("fma.rn.f32x2 %0, %1, %2, %3;" : "=l"(r) : "l"(a), "l"(b), "l"(c)); return r;
}
__device__ __forceinline__ ull add2(ull a, ull b) {
    ull r; asm("add.rn.f32x2 %0, %1, %2;" : "=l"(r) : "l"(a), "l"(b)); return r;
}
__device__ __forceinline__ ull pack2(float v) {
    ull r; asm("mov.b64 %0, {%1, %1};" : "=l"(r) : "f"(v)); return r;
}
__device__ __forceinline__ void unpack2(ull v, float& lo, float& hi) {
    asm("mov.b64 {%0, %1}, %2;" : "=f"(lo), "=f"(hi) : "l"(v));
}

// ---------------------------------------------------------------------------
// Kernel 1: bilinear sampling; emits packed float4 per point.
// ---------------------------------------------------------------------------
__global__ void sample_kernel(const float* __restrict__ src_flow,
                              const float* __restrict__ trg_flow,
                              const float* __restrict__ src_kp,
                              const float* __restrict__ trg_kp) {
    int tid = blockIdx.x * blockDim.x + threadIdx.x;
    if (tid == 0) { g_loss = 0.0; g_vis = 0.0; g_done = 0u; }
    if (tid >= 2 * NB * KK) return;

    int sel = tid >= NB * KK;          // 0 = src, 1 = trg
    int idx = sel ? (tid - NB * KK) : tid;
    const float* flow = sel ? trg_flow : src_flow;
    const float2 p = reinterpret_cast<const float2*>(sel ? trg_kp : src_kp)[idx];

    int   n = idx / KK;

    float x0f = floorf(p.x), y0f = floorf(p.y);
    int   x0  = (int)x0f,    y0  = (int)y0f;
    float wx  = p.x - x0f,   wy  = p.y - y0f;
    int   x1  = x0 + 1,      y1  = y0 + 1;

    int x0c = min(max(x0, 0), RESO - 1);
    int x1c = min(max(x1, 0), RESO - 1);
    int y0c = min(max(y0, 0), RESO - 1);
    int y1c = min(max(y1, 0), RESO - 1);

    float vx0 = (x0 >= 0 && x0 < RESO) ? 1.f : 0.f;
    float vx1 = (x1 >= 0 && x1 < RESO) ? 1.f : 0.f;
    float vy0 = (y0 >= 0 && y0 < RESO) ? 1.f : 0.f;
    float vy1 = (y1 >= 0 && y1 < RESO) ? 1.f : 0.f;

    const float2* base = reinterpret_cast<const float2*>(flow) + (size_t)n * RESO * RESO;

    float2 v00 = base[y0c * RESO + x0c];
    float2 v10 = base[y0c * RESO + x1c];
    float2 v01 = base[y1c * RESO + x0c];
    float2 v11 = base[y1c * RESO + x1c];

    float w00 = (1.f - wx) * (1.f - wy) * vx0 * vy0;
    float w10 = wx * (1.f - wy) * vx1 * vy0;
    float w01 = (1.f - wx) * wy * vx0 * vy1;
    float w11 = wx * wy * vx1 * vy1;

    float cx = v00.x * w00 + v10.x * w10 + v01.x * w01 + v11.x * w11;
    float cy = v00.y * w00 + v10.y * w10 + v01.y * w01 + v11.y * w11;

    if (sel) {
        float txe = cx - EPSF, tye = cy - EPSF;
        g_trg4[idx] = make_float4(txe, tye, txe * txe + tye * tye, 0.f);
    } else {
        // pre-scale |s|^2 by log2e^2 so K2's q is in (log2e*dist)^2 units
        g_src4[idx] = make_float4(cx, cy, (cx * cx + cy * cy) * LOG2E2, 0.f);
    }
}

// ---------------------------------------------------------------------------
// Kernel 2 (fused, single-wave): block = 128 = 32 j x 4 i-octants,
// grid = (K/32, N) = 1024 blocks. 7 blocks/SM resident (launch_bounds) >
// 6.92 needed -> ALL blocks co-resident: no wave quantization tail.
// Per pair: 1 MUFU RSQ + 0.5 MUFU EX2.F16X2 + packed-f32x2 q + cvt packs.
// ---------------------------------------------------------------------------
__global__ void __launch_bounds__(128, 7) loss_kernel(const int* __restrict__ kp_vis,
                                                      const float* __restrict__ kp_wt,
                                                      float* __restrict__ out) {
    __shared__ __align__(16) float s_x[KK];
    __shared__ __align__(16) float s_y[KK];
    __shared__ __align__(16) float s_z[KK];
    __shared__ float s_part[(NOCT - 1) * JCH];
    __shared__ float s_out[2];

    const int n    = blockIdx.y;
    const int tidx = threadIdx.x;
    const int jloc = tidx & (JCH - 1);
    const int oct  = tidx >> 5;                 // i-octant 0..3 (= warp id)
    const int j    = blockIdx.x * JCH + jloc;

    const float4 t = g_trg4[n * KK + j];

    const float4* srcn = g_src4 + n * KK;
    #pragma unroll
    for (int i = tidx; i < KK; i += 128) {
        float4 s = srcn[i];
        s_x[i] = s.x; s_y[i] = s.y; s_z[i] = s.z;
    }
    __syncthreads();

    // q = log2e^2 * dist^2 = z + a*x + b*y + ttC2  (z pre-scaled)
    const float af   = -2.0f * t.x * LOG2E2;
    const float bf   = -2.0f * t.y * LOG2E2;
    const float ttC2 = t.z * LOG2E2;
    const ull a2  = pack2(af);
    const ull b2  = pack2(bf);
    const ull tt2 = pack2(ttC2);

    const float* px = s_x + oct * IO;
    const float* py = s_y + oct * IO;
    const float* pz = s_z + oct * IO;

    float acc[8];
    #pragma unroll
    for (int u = 0; u < 8; u++) acc[u] = 0.f;

    #pragma unroll 2
    for (int i = 0; i < IO; i += 8) {
        ulonglong2 xa = *reinterpret_cast<const ulonglong2*>(px + i);
        ulonglong2 xb = *reinterpret_cast<const ulonglong2*>(px + i + 4);
        ulonglong2 ya = *reinterpret_cast<const ulonglong2*>(py + i);
        ulonglong2 yb = *reinterpret_cast<const ulonglong2*>(py + i + 4);
        ulonglong2 za = *reinterpret_cast<const ulonglong2*>(pz + i);
        ulonglong2 zb = *reinterpret_cast<const ulonglong2*>(pz + i + 4);

        ull q01 = fma2(xa.x, a2, fma2(ya.x, b2, add2(za.x, tt2)));
        ull q23 = fma2(xa.y, a2, fma2(ya.y, b2, add2(za.y, tt2)));
        ull q45 = fma2(xb.x, a2, fma2(yb.x, b2, add2(zb.x, tt2)));
        ull q67 = fma2(xb.y, a2, fma2(yb.y, b2, add2(zb.y, tt2)));

        float q0, q1, q2, q3, q4, q5, q6, q7;
        unpack2(q01, q0, q1);
        unpack2(q23, q2, q3);
        unpack2(q45, q4, q5);
        unpack2(q67, q6, q7);

        // e = -log2e*dist = (-q) * rsq(q); neg folds into the FMUL operand
        float e0 = (-q0) * rsq_approx(q0);
        float e1 = (-q1) * rsq_approx(q1);
        float e2 = (-q2) * rsq_approx(q2);
        float e3 = (-q3) * rsq_approx(q3);
        float e4 = (-q4) * rsq_approx(q4);
        float e5 = (-q5) * rsq_approx(q5);
        float e6 = (-q6) * rsq_approx(q6);
        float e7 = (-q7) * rsq_approx(q7);

        float r0, r1, r2, r3, r4, r5, r6, r7;
        ex2_pair(e0, e1, r0, r1);   // one MUFU op for two exponentials
        ex2_pair(e2, e3, r2, r3);
        ex2_pair(e4, e5, r4, r5);
        ex2_pair(e6, e7, r6, r7);

        acc[0] += r0; acc[1] += r1;
        acc[2] += r2; acc[3] += r3;
        acc[4] += r4; acc[5] += r5;
        acc[6] += r6; acc[7] += r7;
    }
    float accp = ((acc[0] + acc[1]) + (acc[2] + acc[3]))
               + ((acc[4] + acc[5]) + (acc[6] + acc[7]));

    if (oct > 0) s_part[(oct - 1) * JCH + jloc] = accp;
    __syncthreads();

    if (oct == 0) {
        float accv = accp;
        #pragma unroll
        for (int o = 0; o < NOCT - 1; o++) accv += s_part[o * JCH + jloc];

        // diagonal distance (plain units)
        float dx = s_x[j] - t.x, dy = s_y[j] - t.y;
        float djj = sqrt_approx(fmaf(dy, dy, dx * dx));

        float ce = lg2_approx(accv) * LN2 + djj;

        int   vis = (kp_vis[n * KK + j] != 0);
        float wt  = kp_wt[n * KK + j];
        float contrib = vis ? 2.0f * ce * wt : 0.0f;
        float viscnt  = vis ? 1.0f : 0.0f;

        #pragma unroll
        for (int o = 16; o > 0; o >>= 1) {
            contrib += __shfl_down_sync(0xffffffffu, contrib, o);
            viscnt  += __shfl_down_sync(0xffffffffu, viscnt,  o);
        }
        if (jloc == 0) { s_out[0] = contrib; s_out[1] = viscnt; }
    }
    __syncthreads();
    if (tidx == 0) {
        atomicAdd(&g_loss, (double)s_out[0]);
        atomicAdd(&g_vis,  (double)s_out[1]);
        __threadfence();
        unsigned int done = atomicAdd(&g_done, 1u);
        if (done == (KK / JCH) * NB - 1) {
            double L = atomicAdd(&g_loss, 0.0);
            double V = atomicAdd(&g_vis, 0.0);
            out[0] = (float)(L / V);
        }
    }
}

extern "C" void kernel_launch(void* const* d_in, const int* in_sizes, int n_in,
                              void* d_out, int out_size) {
    const float* src_flow = (const float*)d_in[0];
    const float* trg_flow = (const float*)d_in[1];
    const float* src_kp   = (const float*)d_in[2];
    const float* trg_kp   = (const float*)d_in[3];
    const int*   kp_vis   = (const int*)d_in[4];
    const float* kp_wt    = (const float*)d_in[5];
    float* out = (float*)d_out;

    sample_kernel<<<(2 * NB * KK + 255) / 256, 256>>>(src_flow, trg_flow, src_kp, trg_kp);

    dim3 grid(KK / JCH, NB);
    loss_kernel<<<grid, 128>>>(kp_vis, kp_wt, out);
}

// round 14
// speedup vs baseline: 1.0014x; 1.0014x over previous
#include <cuda_runtime.h>
#include <math.h>

#define NB   32
#define RESO 256
#define KK   1024
#define EPSF 1e-6f
#define JCH  32            // j's per block
#define NOCT 4             // i-quarters (warps) per block
#define IO   (KK / NOCT)   // 256 i's per thread

// log2(e)^2 and ln(2)
#define LOG2E2  2.0813689810056077f
#define LN2     0.6931471805599453f

typedef unsigned long long ull;

// Scratch (no allocations allowed).
// src: (sx, sy, |s|^2 * log2e^2, 0)
__device__ float4 g_src4[NB * KK];
__device__ double g_loss;            // zero-init; reset by last loss block
__device__ double g_vis;
__device__ unsigned int g_done;

__device__ __forceinline__ float rsq_approx(float x) {
    float r; asm("rsqrt.approx.f32 %0, %1;" : "=f"(r) : "f"(x)); return r;
}
__device__ __forceinline__ float sqrt_approx(float x) {
    float r; asm("sqrt.approx.f32 %0, %1;" : "=f"(r) : "f"(x)); return r;
}
__device__ __forceinline__ float lg2_approx(float x) {
    float r; asm("lg2.approx.f32 %0, %1;" : "=f"(r) : "f"(x)); return r;
}

// Two exponentials through ONE MUFU ex2.approx.f16x2 op.
__device__ __forceinline__ void ex2_pair(float e0, float e1, float& r0, float& r1) {
    asm("{\n\t"
        ".reg .b32 h;\n\t"
        ".reg .f16 a, b;\n\t"
        "cvt.rn.f16x2.f32 h, %2, %3;\n\t"
        "ex2.approx.f16x2 h, h;\n\t"
        "mov.b32 {a, b}, h;\n\t"
        "cvt.f32.f16 %0, a;\n\t"
        "cvt.f32.f16 %1, b;\n\t"
        "}" : "=f"(r0), "=f"(r1) : "f"(e0), "f"(e1));
}

// packed f32x2 ops (Blackwell; PTX-only)
__device__ __forceinline__ ull fma2(ull a, ull b, ull c) {
    ull r; asm("fma.rn.f32x2 %0, %1, %2, %3;" : "=l"(r) : "l"(a), "l"(b), "l"(c)); return r;
}
__device__ __forceinline__ ull add2(ull a, ull b) {
    ull r; asm("add.rn.f32x2 %0, %1, %2;" : "=l"(r) : "l"(a), "l"(b)); return r;
}
__device__ __forceinline__ ull pack2(float v) {
    ull r; asm("mov.b64 %0, {%1, %1};" : "=l"(r) : "f"(v)); return r;
}
__device__ __forceinline__ void unpack2(ull v, float& lo, float& hi) {
    asm("mov.b64 {%0, %1}, %2;" : "=f"(lo), "=f"(hi) : "l"(v));
}

// ---------------------------------------------------------------------------
// Kernel 1: bilinear sampling of SRC points only.
// ---------------------------------------------------------------------------
__global__ void sample_kernel(const float* __restrict__ src_flow,
                              const float* __restrict__ src_kp) {
    int idx = blockIdx.x * blockDim.x + threadIdx.x;
    if (idx >= NB * KK) return;

    const float2 p = reinterpret_cast<const float2*>(src_kp)[idx];
    int n = idx / KK;

    float x0f = floorf(p.x), y0f = floorf(p.y);
    int   x0  = (int)x0f,    y0  = (int)y0f;
    float wx  = p.x - x0f,   wy  = p.y - y0f;
    int   x1  = x0 + 1,      y1  = y0 + 1;

    int x0c = min(max(x0, 0), RESO - 1);
    int x1c = min(max(x1, 0), RESO - 1);
    int y0c = min(max(y0, 0), RESO - 1);
    int y1c = min(max(y1, 0), RESO - 1);

    float vx0 = (x0 >= 0 && x0 < RESO) ? 1.f : 0.f;
    float vx1 = (x1 >= 0 && x1 < RESO) ? 1.f : 0.f;
    float vy0 = (y0 >= 0 && y0 < RESO) ? 1.f : 0.f;
    float vy1 = (y1 >= 0 && y1 < RESO) ? 1.f : 0.f;

    const float2* base = reinterpret_cast<const float2*>(src_flow) + (size_t)n * RESO * RESO;

    float2 v00 = base[y0c * RESO + x0c];
    float2 v10 = base[y0c * RESO + x1c];
    float2 v01 = base[y1c * RESO + x0c];
    float2 v11 = base[y1c * RESO + x1c];

    float w00 = (1.f - wx) * (1.f - wy) * vx0 * vy0;
    float w10 = wx * (1.f - wy) * vx1 * vy0;
    float w01 = (1.f - wx) * wy * vx0 * vy1;
    float w11 = wx * wy * vx1 * vy1;

    float cx = v00.x * w00 + v10.x * w10 + v01.x * w01 + v11.x * w11;
    float cy = v00.y * w00 + v10.y * w10 + v01.y * w01 + v11.y * w11;

    // pre-scale |s|^2 by log2e^2 so K2's q is in (log2e*dist)^2 units
    g_src4[idx] = make_float4(cx, cy, (cx * cx + cy * cy) * LOG2E2, 0.f);
}

// ---------------------------------------------------------------------------
// Kernel 2 (fused): block = 128 = 32 j x 4 i-quarters, grid = (K/32, N).
// Inline trg sampling: each thread gathers ONE corner of one trg keypoint
// (32 j x 4 corners = 128 threads), shuffle-reduced in groups of 4 ->
// overlaps with the 16 KB src smem fill. Last finishing block writes out[0]
// and resets the global accumulators for the next replay.
// ---------------------------------------------------------------------------
__global__ void __launch_bounds__(128, 7) loss_kernel(const float* __restrict__ trg_flow,
                                                      const float* __restrict__ trg_kp,
                                                      const int* __restrict__ kp_vis,
                                                      const float* __restrict__ kp_wt,
                                                      float* __restrict__ out) {
    __shared__ __align__(16) float s_x[KK];
    __shared__ __align__(16) float s_y[KK];
    __shared__ __align__(16) float s_z[KK];
    __shared__ float4 s_t[JCH];
    __shared__ float  s_part[(NOCT - 1) * JCH];
    __shared__ float  s_out[2];

    const int n    = blockIdx.y;
    const int tidx = threadIdx.x;
    const int jloc = tidx & (JCH - 1);
    const int oct  = tidx >> 5;                 // i-quarter 0..3 (= warp id)

    // ---- inline trg sampling: thread = (j32, corner) ----
    {
        int j32 = tidx >> 2;           // 0..31
        int c   = tidx & 3;            // corner
        const float2 p = reinterpret_cast<const float2*>(trg_kp)[n * KK + blockIdx.x * JCH + j32];

        float x0f = floorf(p.x), y0f = floorf(p.y);
        int   xi  = (int)x0f + (c & 1);
        int   yi  = (int)y0f + (c >> 1);
        float wxc = (c & 1)  ? (p.x - x0f) : (1.f - (p.x - x0f));
        float wyc = (c >> 1) ? (p.y - y0f) : (1.f - (p.y - y0f));

        int   xc = min(max(xi, 0), RESO - 1);
        int   yc = min(max(yi, 0), RESO - 1);
        float vv = (xi >= 0 && xi < RESO && yi >= 0 && yi < RESO) ? 1.f : 0.f;

        float2 v = reinterpret_cast<const float2*>(trg_flow)[(size_t)n * RESO * RESO + yc * RESO + xc];
        float w  = wxc * wyc * vv;
        float cx = v.x * w;
        float cy = v.y * w;

        cx += __shfl_down_sync(0xffffffffu, cx, 1);
        cy += __shfl_down_sync(0xffffffffu, cy, 1);
        cx += __shfl_down_sync(0xffffffffu, cx, 2);
        cy += __shfl_down_sync(0xffffffffu, cy, 2);
        if (c == 0) {
            float txe = cx - EPSF, tye = cy - EPSF;
            s_t[j32] = make_float4(txe, tye, txe * txe + tye * tye, 0.f);
        }
    }

    // ---- src smem fill (overlaps with the trg gather latency above) ----
    const float4* srcn = g_src4 + n * KK;
    #pragma unroll
    for (int i = tidx; i < KK; i += 128) {
        float4 s = srcn[i];
        s_x[i] = s.x; s_y[i] = s.y; s_z[i] = s.z;
    }
    __syncthreads();

    const float4 t = s_t[jloc];
    const int    j = blockIdx.x * JCH + jloc;

    // q = log2e^2 * dist^2 = z + a*x + b*y + ttC2  (z pre-scaled)
    const float af   = -2.0f * t.x * LOG2E2;
    const float bf   = -2.0f * t.y * LOG2E2;
    const float ttC2 = t.z * LOG2E2;
    const ull a2  = pack2(af);
    const ull b2  = pack2(bf);
    const ull tt2 = pack2(ttC2);

    const float* px = s_x + oct * IO;
    const float* py = s_y + oct * IO;
    const float* pz = s_z + oct * IO;

    float acc[8];
    #pragma unroll
    for (int u = 0; u < 8; u++) acc[u] = 0.f;

    #pragma unroll 2
    for (int i = 0; i < IO; i += 8) {
        ulonglong2 xa = *reinterpret_cast<const ulonglong2*>(px + i);
        ulonglong2 xb = *reinterpret_cast<const ulonglong2*>(px + i + 4);
        ulonglong2 ya = *reinterpret_cast<const ulonglong2*>(py + i);
        ulonglong2 yb = *reinterpret_cast<const ulonglong2*>(py + i + 4);
        ulonglong2 za = *reinterpret_cast<const ulonglong2*>(pz + i);
        ulonglong2 zb = *reinterpret_cast<const ulonglong2*>(pz + i + 4);

        ull q01 = fma2(xa.x, a2, fma2(ya.x, b2, add2(za.x, tt2)));
        ull q23 = fma2(xa.y, a2, fma2(ya.y, b2, add2(za.y, tt2)));
        ull q45 = fma2(xb.x, a2, fma2(yb.x, b2, add2(zb.x, tt2)));
        ull q67 = fma2(xb.y, a2, fma2(yb.y, b2, add2(zb.y, tt2)));

        float q0, q1, q2, q3, q4, q5, q6, q7;
        unpack2(q01, q0, q1);
        unpack2(q23, q2, q3);
        unpack2(q45, q4, q5);
        unpack2(q67, q6, q7);

        // e = -log2e*dist = (-q) * rsq(q); neg folds into the FMUL operand
        float e0 = (-q0) * rsq_approx(q0);
        float e1 = (-q1) * rsq_approx(q1);
        float e2 = (-q2) * rsq_approx(q2);
        float e3 = (-q3) * rsq_approx(q3);
        float e4 = (-q4) * rsq_approx(q4);
        float e5 = (-q5) * rsq_approx(q5);
        float e6 = (-q6) * rsq_approx(q6);
        float e7 = (-q7) * rsq_approx(q7);

        float r0, r1, r2, r3, r4, r5, r6, r7;
        ex2_pair(e0, e1, r0, r1);   // one MUFU op for two exponentials
        ex2_pair(e2, e3, r2, r3);
        ex2_pair(e4, e5, r4, r5);
        ex2_pair(e6, e7, r6, r7);

        acc[0] += r0; acc[1] += r1;
        acc[2] += r2; acc[3] += r3;
        acc[4] += r4; acc[5] += r5;
        acc[6] += r6; acc[7] += r7;
    }
    float accp = ((acc[0] + acc[1]) + (acc[2] + acc[3]))
               + ((acc[4] + acc[5]) + (acc[6] + acc[7]));

    if (oct > 0) s_part[(oct - 1) * JCH + jloc] = accp;
    __syncthreads();

    if (oct == 0) {
        float accv = accp;
        #pragma unroll
        for (int o = 0; o < NOCT - 1; o++) accv += s_part[o * JCH + jloc];

        // diagonal distance (plain units)
        float dx = s_x[j] - t.x, dy = s_y[j] - t.y;
        float djj = sqrt_approx(fmaf(dy, dy, dx * dx));

        float ce = lg2_approx(accv) * LN2 + djj;

        int   vis = (kp_vis[n * KK + j] != 0);
        float wt  = kp_wt[n * KK + j];
        float contrib = vis ? 2.0f * ce * wt : 0.0f;
        float viscnt  = vis ? 1.0f : 0.0f;

        #pragma unroll
        for (int o = 16; o > 0; o >>= 1) {
            contrib += __shfl_down_sync(0xffffffffu, contrib, o);
            viscnt  += __shfl_down_sync(0xffffffffu, viscnt,  o);
        }
        if (jloc == 0) { s_out[0] = contrib; s_out[1] = viscnt; }
    }
    __syncthreads();
    if (tidx == 0) {
        atomicAdd(&g_loss, (double)s_out[0]);
        atomicAdd(&g_vis,  (double)s_out[1]);
        __threadfence();
        unsigned int done = atomicAdd(&g_done, 1u);
        if (done == (KK / JCH) * NB - 1) {
            double L = atomicAdd(&g_loss, 0.0);
            double V = atomicAdd(&g_vis, 0.0);
            out[0] = (float)(L / V);
            // reset for the next graph replay (all blocks have arrived)
            g_loss = 0.0;
            g_vis  = 0.0;
            __threadfence();
            g_done = 0u;
        }
    }
}

extern "C" void kernel_launch(void* const* d_in, const int* in_sizes, int n_in,
                              void* d_out, int out_size) {
    const float* src_flow = (const float*)d_in[0];
    const float* trg_flow = (const float*)d_in[1];
    const float* src_kp   = (const float*)d_in[2];
    const float* trg_kp   = (const float*)d_in[3];
    const int*   kp_vis   = (const int*)d_in[4];
    const float* kp_wt    = (const float*)d_in[5];
    float* out = (float*)d_out;

    sample_kernel<<<(NB * KK + 255) / 256, 256>>>(src_flow, src_kp);

    dim3 grid(KK / JCH, NB);
    loss_kernel<<<grid, 128>>>(trg_flow, trg_kp, kp_vis, kp_wt, out);
}